// round 2
// baseline (speedup 1.0000x reference)
#include <cuda_runtime.h>
#include <cstdint>

#define NN   100000
#define INC  128
#define HIDF 16
#define OUTF 64

// Scratch (static device globals — no allocation allowed). 16B-aligned for v4 ops.
__device__ __align__(16) float g_dinv[NN];
__device__ __align__(16) float g_h1[NN * HIDF];
__device__ __align__(16) float g_out1[NN * HIDF];
__device__ __align__(16) float g_h2[NN * OUTF];

// Vectorized global reduction: one LTS op for 16 bytes (sm_90+).
__device__ __forceinline__ void red_add_v4(float* addr, float4 v) {
    asm volatile("red.global.add.v4.f32 [%0], {%1, %2, %3, %4};"
                 :: "l"(addr), "f"(v.x), "f"(v.y), "f"(v.z), "f"(v.w)
                 : "memory");
}

// ---------------- degree / dinv ----------------
__global__ void k_deg_init() {
    int i = blockIdx.x * blockDim.x + threadIdx.x;
    if (i < NN) g_dinv[i] = 1.0f;  // self loop
}

__global__ void k_deg_edges(const int* __restrict__ col, int E) {
    int i = blockIdx.x * blockDim.x + threadIdx.x;
    if (i < E) atomicAdd(&g_dinv[col[i]], 1.0f);
}

__global__ void k_dinv() {
    int i = blockIdx.x * blockDim.x + threadIdx.x;
    if (i < NN) g_dinv[i] = rsqrtf(g_dinv[i]);  // deg >= 1 always
}

// ---------------- GEMM1 + init1: h1 = x @ W1; out1 = dinv^2*h1 + b1 ----------------
// 256 threads/block, 16 nodes per block. Stage W1 (8KB) + 16 x-rows (8KB) in smem.
__global__ void k_gemm1(const float* __restrict__ x, const float* __restrict__ W1,
                        const float* __restrict__ b1) {
    __shared__ float sW[INC * HIDF];   // 2048 floats
    __shared__ float sX[16 * INC];     // 2048 floats
    int tid = threadIdx.x;
    int nodeBase = blockIdx.x * 16;
    #pragma unroll
    for (int i = tid; i < INC * HIDF; i += 256) sW[i] = W1[i];
    for (int i = tid; i < 16 * INC; i += 256) {
        int node = nodeBase + (i >> 7);
        sX[i] = (node < NN) ? x[(size_t)node * INC + (i & 127)] : 0.0f;
    }
    __syncthreads();
    int ln = tid >> 4;          // local node 0..15
    int h  = tid & 15;          // hid feature
    int node = nodeBase + ln;
    if (node >= NN) return;
    float acc = 0.0f;
    const float* xr = sX + ln * INC;
    #pragma unroll 8
    for (int k = 0; k < INC; k++) acc += xr[k] * sW[k * HIDF + h];
    g_h1[node * HIDF + h] = acc;
    float d = g_dinv[node];
    g_out1[node * HIDF + h] = d * d * acc + b1[h];
}

// ---------------- edge scatter layer 1: 1 thread/edge, 4x (ld.128 + red.v4) ----------------
__global__ void k_edge1(const int* __restrict__ row, const int* __restrict__ col, int E) {
    int e = blockIdx.x * blockDim.x + threadIdx.x;
    if (e >= E) return;
    int r = row[e];
    int c = col[e];
    float norm = g_dinv[r] * g_dinv[c];
    const float4* src = reinterpret_cast<const float4*>(g_h1 + r * HIDF);
    float* dst = g_out1 + c * HIDF;
    #pragma unroll
    for (int q = 0; q < 4; q++) {
        float4 h = src[q];
        h.x *= norm; h.y *= norm; h.z *= norm; h.w *= norm;
        red_add_v4(dst + q * 4, h);
    }
}

// ---------------- GEMM2 + relu + init2: h2 = relu(out1) @ W2; out = dinv^2*h2 + b2 ----------------
// 256 threads/block, 4 nodes per block.
__global__ void k_gemm2(const float* __restrict__ W2, const float* __restrict__ b2,
                        float* __restrict__ out) {
    __shared__ float sW[HIDF * OUTF];  // 1024 floats
    __shared__ float sH[4 * HIDF];     // 64 floats
    int tid = threadIdx.x;
    int nodeBase = blockIdx.x * 4;
    for (int i = tid; i < HIDF * OUTF; i += 256) sW[i] = W2[i];
    if (tid < 4 * HIDF) {
        int node = nodeBase + (tid >> 4);
        float v = (node < NN) ? g_out1[node * HIDF + (tid & 15)] : 0.0f;
        sH[tid] = fmaxf(v, 0.0f);  // fused ReLU
    }
    __syncthreads();
    int ln = tid >> 6;         // 0..3
    int o  = tid & 63;
    int node = nodeBase + ln;
    if (node >= NN) return;
    float acc = 0.0f;
    const float* hr = sH + ln * HIDF;
    #pragma unroll
    for (int k = 0; k < HIDF; k++) acc += hr[k] * sW[k * OUTF + o];
    g_h2[node * OUTF + o] = acc;
    float d = g_dinv[node];
    out[node * OUTF + o] = d * d * acc + b2[o];  // init d_out (covers poison)
}

// ---------------- edge scatter layer 2: 4 threads/edge, each 4x (ld.128 + red.v4) ----------------
__global__ void k_edge2(const int* __restrict__ row, const int* __restrict__ col,
                        float* __restrict__ out, int E) {
    int t = blockIdx.x * blockDim.x + threadIdx.x;
    if (t >= E * 4) return;
    int e = t >> 2, q = t & 3;       // q selects 16-float chunk
    int r = row[e];
    int c = col[e];
    float norm = g_dinv[r] * g_dinv[c];
    const float4* src = reinterpret_cast<const float4*>(g_h2 + r * OUTF + q * 16);
    float* dst = out + c * OUTF + q * 16;
    #pragma unroll
    for (int u = 0; u < 4; u++) {
        float4 h = src[u];
        h.x *= norm; h.y *= norm; h.z *= norm; h.w *= norm;
        red_add_v4(dst + u * 4, h);
    }
}

extern "C" void kernel_launch(void* const* d_in, const int* in_sizes, int n_in,
                              void* d_out, int out_size) {
    const float* x   = (const float*)d_in[0];
    const int*   ei  = (const int*)d_in[1];   // int32! (JAX x64 disabled)
    const float* W1  = (const float*)d_in[2];
    const float* b1  = (const float*)d_in[3];
    const float* W2  = (const float*)d_in[4];
    const float* b2  = (const float*)d_in[5];
    float*       out = (float*)d_out;

    const int E = in_sizes[1] / 2;
    const int* row = ei;       // edge_index[0] = sources
    const int* col = ei + E;   // edge_index[1] = targets (aggregation index)

    const int T = 256;
    auto cdiv = [](long long a, long long b) { return (int)((a + b - 1) / b); };

    k_deg_init<<<cdiv(NN, T), T>>>();
    k_deg_edges<<<cdiv(E, T), T>>>(col, E);
    k_dinv<<<cdiv(NN, T), T>>>();

    k_gemm1<<<cdiv(NN, 16), T>>>(x, W1, b1);
    k_edge1<<<cdiv(E, T), T>>>(row, col, E);

    k_gemm2<<<cdiv(NN, 4), T>>>(W2, b2, out);
    k_edge2<<<cdiv((long long)E * 4, T), T>>>(row, col, out, E);
}

// round 3
// speedup vs baseline: 1.1707x; 1.1707x over previous
#include <cuda_runtime.h>
#include <cstdint>

#define NN    100000
#define INC   128
#define HIDF  16
#define OUTF  64
#define EMAX  3200000

// ---- Scratch (static device globals — no allocation allowed) ----
__device__ __align__(16) float g_dinv[NN];
__device__ __align__(16) float g_h1[NN * HIDF];
__device__ __align__(16) float g_out1[NN * HIDF];
__device__ __align__(16) float g_h2[NN * OUTF];
__device__ int g_cnt[NN];          // per-target edge count (no self loop)
__device__ int g_rowstart[NN];     // CSR row offsets (exclusive scan of cnt)
__device__ int g_cursor[NN];       // scatter cursors (copy of rowstart)
__device__ int g_csrc[EMAX];       // CSR: source node per (target-sorted) edge

// ---------------- zero counters ----------------
__global__ void k_zero() {
    int i = blockIdx.x * blockDim.x + threadIdx.x;
    if (i < NN) g_cnt[i] = 0;
}

// ---------------- histogram by target ----------------
__global__ void k_hist(const int* __restrict__ col, int E) {
    int i = blockIdx.x * blockDim.x + threadIdx.x;
    if (i < E) atomicAdd(&g_cnt[col[i]], 1);
}

// ---------------- single-block chunked exclusive scan -> rowstart, cursor ----------------
__global__ void k_scan() {
    __shared__ int ssum[1024];
    int t = threadIdx.x;
    const int CH = (NN + 1023) / 1024;  // 98
    int base = t * CH;
    int s = 0;
    for (int j = 0; j < CH; j++) {
        int idx = base + j;
        if (idx < NN) s += g_cnt[idx];
    }
    ssum[t] = s;
    __syncthreads();
    // Hillis-Steele inclusive scan
    for (int off = 1; off < 1024; off <<= 1) {
        int v = 0;
        if (t >= off) v = ssum[t - off];
        __syncthreads();
        if (t >= off) ssum[t] += v;
        __syncthreads();
    }
    int running = (t == 0) ? 0 : ssum[t - 1];  // exclusive prefix of this chunk
    for (int j = 0; j < CH; j++) {
        int idx = base + j;
        if (idx < NN) {
            g_rowstart[idx] = running;
            g_cursor[idx]   = running;
            running += g_cnt[idx];
        }
    }
}

// ---------------- dinv = rsqrt(deg + selfloop) ----------------
__global__ void k_dinv() {
    int i = blockIdx.x * blockDim.x + threadIdx.x;
    if (i < NN) g_dinv[i] = rsqrtf((float)(g_cnt[i] + 1));
}

// ---------------- scatter edges into CSR (sorted by target) ----------------
__global__ void k_scatter(const int* __restrict__ row, const int* __restrict__ col, int E) {
    int e = blockIdx.x * blockDim.x + threadIdx.x;
    if (e >= E) return;
    int c = col[e];
    int pos = atomicAdd(&g_cursor[c], 1);
    g_csrc[pos] = row[e];
}

// ---------------- GEMM1: h1 = x @ W1 (register-tiled 2n x 4h) ----------------
// 128 threads/block, 64 nodes/block. smem x padded to stride 129 (conflict-free).
__global__ void k_gemm1(const float* __restrict__ x, const float* __restrict__ W1) {
    __shared__ float sX[64 * 129];           // 33 KB
    __shared__ __align__(16) float sW[INC * HIDF];  // 8 KB
    int tid = threadIdx.x;
    int nodeBase = blockIdx.x * 64;
    for (int i = tid; i < INC * HIDF; i += 128) sW[i] = W1[i];
    for (int i = tid; i < 64 * INC; i += 128) {
        int r = i >> 7, ck = i & 127;
        int node = nodeBase + r;
        sX[r * 129 + ck] = (node < NN) ? x[(size_t)node * INC + ck] : 0.0f;
    }
    __syncthreads();
    int npair = tid >> 2;      // 0..31 -> rows 2*npair, 2*npair+1
    int hq    = tid & 3;       // h quad: features 4*hq..4*hq+3
    float4 acc0 = {0, 0, 0, 0}, acc1 = {0, 0, 0, 0};
    const float* xr0 = sX + (npair * 2) * 129;
    const float* xr1 = xr0 + 129;
    #pragma unroll 8
    for (int k = 0; k < INC; k++) {
        float  xa = xr0[k], xb = xr1[k];
        float4 w  = *reinterpret_cast<const float4*>(sW + k * HIDF + hq * 4);
        acc0.x += xa * w.x; acc0.y += xa * w.y; acc0.z += xa * w.z; acc0.w += xa * w.w;
        acc1.x += xb * w.x; acc1.y += xb * w.y; acc1.z += xb * w.z; acc1.w += xb * w.w;
    }
    int n0 = nodeBase + npair * 2;
    if (n0 < NN)     *reinterpret_cast<float4*>(g_h1 + n0 * HIDF + hq * 4)       = acc0;
    if (n0 + 1 < NN) *reinterpret_cast<float4*>(g_h1 + (n0 + 1) * HIDF + hq * 4) = acc1;
}

// ---------------- agg layer 1: warp per node, no atomics ----------------
// out1[c] = dinv[c] * ( sum_nbr dinv[s]*h1[s] + dinv[c]*h1[c] ) + b1
__global__ void k_agg1(const float* __restrict__ b1) {
    int warp = (blockIdx.x * blockDim.x + threadIdx.x) >> 5;
    int lane = threadIdx.x & 31;
    if (warp >= NN) return;
    int c = warp;
    int f = lane & 15, half = lane >> 4;
    int start = g_rowstart[c], deg = g_cnt[c];
    float acc = 0.0f;
    for (int i = half; i < deg; i += 2) {
        int s = g_csrc[start + i];
        acc += g_dinv[s] * g_h1[s * HIDF + f];
    }
    acc += __shfl_xor_sync(0xFFFFFFFFu, acc, 16);
    if (half == 0) {
        float dc = g_dinv[c];
        float total = acc + dc * g_h1[c * HIDF + f];
        g_out1[c * HIDF + f] = dc * total + b1[f];
    }
}

// ---------------- GEMM2 + ReLU: h2 = relu(out1) @ W2 ----------------
// 1024 threads/block, 16 nodes/block.
__global__ void k_gemm2(const float* __restrict__ W2) {
    __shared__ float sW[HIDF * OUTF];   // 1024 floats
    __shared__ float sH[16 * HIDF];     // 256 floats
    int tid = threadIdx.x;
    int nodeBase = blockIdx.x * 16;
    if (tid < HIDF * OUTF) sW[tid] = W2[tid];
    if (tid < 16 * HIDF) {
        int node = nodeBase + (tid >> 4);
        float v = (node < NN) ? g_out1[node * HIDF + (tid & 15)] : 0.0f;
        sH[tid] = fmaxf(v, 0.0f);   // fused ReLU
    }
    __syncthreads();
    int ln = tid >> 6;     // 0..15
    int o  = tid & 63;
    int node = nodeBase + ln;
    if (node >= NN) return;
    float acc = 0.0f;
    const float* hr = sH + ln * HIDF;
    #pragma unroll
    for (int k = 0; k < HIDF; k++) acc += hr[k] * sW[k * OUTF + o];
    g_h2[node * OUTF + o] = acc;
}

// ---------------- agg layer 2: warp per node, float2 per lane, no atomics ----------------
// out[c] = dinv[c] * ( sum_nbr dinv[s]*h2[s] + dinv[c]*h2[c] ) + b2
__global__ void k_agg2(float* __restrict__ out, const float* __restrict__ b2) {
    int warp = (blockIdx.x * blockDim.x + threadIdx.x) >> 5;
    int lane = threadIdx.x & 31;
    if (warp >= NN) return;
    int c = warp;
    int start = g_rowstart[c], deg = g_cnt[c];
    float2 acc = {0.0f, 0.0f};
    int i = 0;
    for (; i + 1 < deg; i += 2) {
        int s0 = g_csrc[start + i];
        int s1 = g_csrc[start + i + 1];
        float d0 = g_dinv[s0], d1 = g_dinv[s1];
        float2 v0 = reinterpret_cast<const float2*>(g_h2 + s0 * OUTF)[lane];
        float2 v1 = reinterpret_cast<const float2*>(g_h2 + s1 * OUTF)[lane];
        acc.x += d0 * v0.x + d1 * v1.x;
        acc.y += d0 * v0.y + d1 * v1.y;
    }
    if (i < deg) {
        int s = g_csrc[start + i];
        float d = g_dinv[s];
        float2 v = reinterpret_cast<const float2*>(g_h2 + s * OUTF)[lane];
        acc.x += d * v.x;
        acc.y += d * v.y;
    }
    float dc = g_dinv[c];
    float2 self = reinterpret_cast<const float2*>(g_h2 + c * OUTF)[lane];
    float2 r;
    r.x = dc * (acc.x + dc * self.x) + b2[2 * lane];
    r.y = dc * (acc.y + dc * self.y) + b2[2 * lane + 1];
    reinterpret_cast<float2*>(out + c * OUTF)[lane] = r;
}

extern "C" void kernel_launch(void* const* d_in, const int* in_sizes, int n_in,
                              void* d_out, int out_size) {
    const float* x   = (const float*)d_in[0];
    const int*   ei  = (const int*)d_in[1];   // int32 (JAX x64 disabled)
    const float* W1  = (const float*)d_in[2];
    const float* b1  = (const float*)d_in[3];
    const float* W2  = (const float*)d_in[4];
    const float* b2  = (const float*)d_in[5];
    float*       out = (float*)d_out;

    const int E = in_sizes[1] / 2;
    const int* row = ei;       // sources
    const int* col = ei + E;   // targets (aggregation index)

    const int T = 256;
    auto cdiv = [](long long a, long long b) { return (int)((a + b - 1) / b); };

    // CSR build + norms
    k_zero<<<cdiv(NN, T), T>>>();
    k_hist<<<cdiv(E, T), T>>>(col, E);
    k_scan<<<1, 1024>>>();
    k_dinv<<<cdiv(NN, T), T>>>();
    k_scatter<<<cdiv(E, T), T>>>(row, col, E);

    // layer 1
    k_gemm1<<<cdiv(NN, 64), 128>>>(x, W1);
    k_agg1<<<cdiv((long long)NN * 32, T), T>>>(b1);

    // layer 2
    k_gemm2<<<cdiv(NN, 16), 1024>>>(W2);
    k_agg2<<<cdiv((long long)NN * 32, T), T>>>(out, b2);
}

// round 4
// speedup vs baseline: 2.1485x; 1.8352x over previous
#include <cuda_runtime.h>
#include <cstdint>

#define NN    100000
#define INC   128
#define HIDF  16
#define OUTF  64
#define EMAX  3200000
#define SCAN_B 1024
#define NBLK  ((NN + SCAN_B - 1) / SCAN_B)   // 98

// ---- Scratch (static device globals — no allocation allowed) ----
__device__ __align__(16) float g_dinv[NN];
__device__ __align__(16) float g_h1[NN * HIDF];   // stores dinv[n] * (x@W1)[n]
__device__ __align__(16) float g_h2[NN * OUTF];   // stores dinv[n] * h2[n]
__device__ int g_cnt[NN];          // per-target edge count (no self loop)
__device__ int g_rowstart[NN];     // CSR row offsets
__device__ int g_cursor[NN];       // scatter cursors
__device__ int g_csrc[EMAX];       // CSR: source node per (target-sorted) edge
__device__ int g_bsum[NBLK];       // per-block count sums
__device__ int g_boff[NBLK];       // exclusive block offsets

// ---------------- zero counters ----------------
__global__ void k_zero() {
    int i = blockIdx.x * blockDim.x + threadIdx.x;
    if (i < NN) g_cnt[i] = 0;
}

// ---------------- histogram by target ----------------
__global__ void k_hist(const int* __restrict__ col, int E) {
    int i = blockIdx.x * blockDim.x + threadIdx.x;
    if (i < E) atomicAdd(&g_cnt[col[i]], 1);
}

// ---------------- scan stage 1: coalesced per-block sums ----------------
__global__ void k_blocksum() {
    __shared__ int wsum[32];
    int i = blockIdx.x * SCAN_B + threadIdx.x;
    int v = (i < NN) ? g_cnt[i] : 0;
    #pragma unroll
    for (int o = 16; o > 0; o >>= 1) v += __shfl_xor_sync(0xFFFFFFFFu, v, o);
    int warp = threadIdx.x >> 5, lane = threadIdx.x & 31;
    if (lane == 0) wsum[warp] = v;
    __syncthreads();
    if (warp == 0) {
        int s = (lane < SCAN_B / 32) ? wsum[lane] : 0;
        #pragma unroll
        for (int o = 16; o > 0; o >>= 1) s += __shfl_xor_sync(0xFFFFFFFFu, s, o);
        if (lane == 0) g_bsum[blockIdx.x] = s;
    }
}

// ---------------- scan stage 2: tiny scan of NBLK block sums ----------------
__global__ void k_scanbsum() {
    __shared__ int s[128];
    int t = threadIdx.x;
    int v = (t < NBLK) ? g_bsum[t] : 0;
    s[t] = v;
    __syncthreads();
    for (int off = 1; off < 128; off <<= 1) {
        int y = (t >= off) ? s[t - off] : 0;
        __syncthreads();
        s[t] += y;
        __syncthreads();
    }
    if (t < NBLK) g_boff[t] = s[t] - v;   // exclusive
}

// ---------------- scan stage 3: per-block exclusive scan + dinv ----------------
__global__ void k_applyscan() {
    __shared__ int wtot[33];
    int i = blockIdx.x * SCAN_B + threadIdx.x;
    int warp = threadIdx.x >> 5, lane = threadIdx.x & 31;
    int v = (i < NN) ? g_cnt[i] : 0;
    // inclusive warp scan
    int x = v;
    #pragma unroll
    for (int o = 1; o < 32; o <<= 1) {
        int y = __shfl_up_sync(0xFFFFFFFFu, x, o);
        if (lane >= o) x += y;
    }
    if (lane == 31) wtot[warp] = x;
    __syncthreads();
    if (warp == 0) {
        int t = (lane < SCAN_B / 32) ? wtot[lane] : 0;
        int tx = t;
        #pragma unroll
        for (int o = 1; o < 32; o <<= 1) {
            int y = __shfl_up_sync(0xFFFFFFFFu, tx, o);
            if (lane >= o) tx += y;
        }
        wtot[lane + 1] = tx;            // inclusive -> exclusive via +1 shift
        if (lane == 0) wtot[0] = 0;
    }
    __syncthreads();
    if (i < NN) {
        int start = g_boff[blockIdx.x] + wtot[warp] + (x - v);
        g_rowstart[i] = start;
        g_cursor[i]   = start;
        g_dinv[i]     = rsqrtf((float)(v + 1));
    }
}

// ---------------- scatter edges into CSR (sorted by target) ----------------
__global__ void k_scatter(const int* __restrict__ row, const int* __restrict__ col, int E) {
    int e = blockIdx.x * blockDim.x + threadIdx.x;
    if (e >= E) return;
    int c = col[e];
    int pos = atomicAdd(&g_cursor[c], 1);
    g_csrc[pos] = row[e];
}

// ---------------- GEMM1: ĥ1 = dinv * (x @ W1) (register-tiled 2n x 4h) ----------------
__global__ void k_gemm1(const float* __restrict__ x, const float* __restrict__ W1) {
    __shared__ float sX[64 * 129];                  // padded, conflict-free
    __shared__ __align__(16) float sW[INC * HIDF];
    int tid = threadIdx.x;
    int nodeBase = blockIdx.x * 64;
    for (int i = tid; i < INC * HIDF; i += 128) sW[i] = W1[i];
    for (int i = tid; i < 64 * INC; i += 128) {
        int r = i >> 7, ck = i & 127;
        int node = nodeBase + r;
        sX[r * 129 + ck] = (node < NN) ? x[(size_t)node * INC + ck] : 0.0f;
    }
    __syncthreads();
    int npair = tid >> 2;
    int hq    = tid & 3;
    float4 acc0 = {0, 0, 0, 0}, acc1 = {0, 0, 0, 0};
    const float* xr0 = sX + (npair * 2) * 129;
    const float* xr1 = xr0 + 129;
    #pragma unroll 8
    for (int k = 0; k < INC; k++) {
        float  xa = xr0[k], xb = xr1[k];
        float4 w  = *reinterpret_cast<const float4*>(sW + k * HIDF + hq * 4);
        acc0.x += xa * w.x; acc0.y += xa * w.y; acc0.z += xa * w.z; acc0.w += xa * w.w;
        acc1.x += xb * w.x; acc1.y += xb * w.y; acc1.z += xb * w.z; acc1.w += xb * w.w;
    }
    int n0 = nodeBase + npair * 2;
    if (n0 < NN) {
        float d = g_dinv[n0];
        acc0.x *= d; acc0.y *= d; acc0.z *= d; acc0.w *= d;
        *reinterpret_cast<float4*>(g_h1 + n0 * HIDF + hq * 4) = acc0;
    }
    if (n0 + 1 < NN) {
        float d = g_dinv[n0 + 1];
        acc1.x *= d; acc1.y *= d; acc1.z *= d; acc1.w *= d;
        *reinterpret_cast<float4*>(g_h1 + (n0 + 1) * HIDF + hq * 4) = acc1;
    }
}

// ---------------- fused agg1 + ReLU + GEMM2: warp per node ----------------
// out1 = dc * (Σ ĥ1[s] + ĥ1[c]) + b1 ; a = relu(out1) ; ĥ2 = dc * (a @ W2)
__global__ void k_agg1g2(const float* __restrict__ b1, const float* __restrict__ W2) {
    __shared__ float sW[HIDF * OUTF];   // 4 KB
    int tid = threadIdx.x;
    for (int i = tid; i < HIDF * OUTF; i += blockDim.x) sW[i] = W2[i];
    __syncthreads();
    int warpg = (blockIdx.x * blockDim.x + tid) >> 5;
    int lane = tid & 31;
    if (warpg >= NN) return;
    int c = warpg;
    int f = lane & 15, half = lane >> 4;
    int start = g_rowstart[c], deg = g_cnt[c];
    float acc = 0.0f;
    for (int i = half; i < deg; i += 2) {
        int s = g_csrc[start + i];
        acc += g_h1[s * HIDF + f];       // prescaled by dinv[s]
    }
    acc += __shfl_xor_sync(0xFFFFFFFFu, acc, 16);   // all 32 lanes: sum for feature f
    float dc = g_dinv[c];
    float a = dc * (acc + g_h1[c * HIDF + f]) + b1[f];
    a = fmaxf(a, 0.0f);                              // fused ReLU
    // matvec: lane computes outputs 2*lane, 2*lane+1
    float2 h2 = {0.0f, 0.0f};
    #pragma unroll
    for (int k = 0; k < HIDF; k++) {
        float ak = __shfl_sync(0xFFFFFFFFu, a, k);   // a_k (lanes 0..15 hold a)
        float2 w = reinterpret_cast<const float2*>(sW + k * OUTF)[lane];
        h2.x += ak * w.x;
        h2.y += ak * w.y;
    }
    h2.x *= dc; h2.y *= dc;                          // prescale ĥ2 = dinv*h2
    reinterpret_cast<float2*>(g_h2 + c * OUTF)[lane] = h2;
}

// ---------------- agg layer 2: warp per node, 4-edge unroll, no atomics ----------------
// out[c] = dc * (Σ ĥ2[s] + ĥ2[c]) + b2
__global__ void k_agg2(float* __restrict__ out, const float* __restrict__ b2) {
    int warpg = (blockIdx.x * blockDim.x + threadIdx.x) >> 5;
    int lane = threadIdx.x & 31;
    if (warpg >= NN) return;
    int c = warpg;
    int start = g_rowstart[c], deg = g_cnt[c];
    float2 acc = {0.0f, 0.0f};
    int i = 0;
    for (; i + 3 < deg; i += 4) {
        int s0 = g_csrc[start + i];
        int s1 = g_csrc[start + i + 1];
        int s2 = g_csrc[start + i + 2];
        int s3 = g_csrc[start + i + 3];
        float2 v0 = reinterpret_cast<const float2*>(g_h2 + s0 * OUTF)[lane];
        float2 v1 = reinterpret_cast<const float2*>(g_h2 + s1 * OUTF)[lane];
        float2 v2 = reinterpret_cast<const float2*>(g_h2 + s2 * OUTF)[lane];
        float2 v3 = reinterpret_cast<const float2*>(g_h2 + s3 * OUTF)[lane];
        acc.x += v0.x + v1.x + v2.x + v3.x;
        acc.y += v0.y + v1.y + v2.y + v3.y;
    }
    for (; i < deg; i++) {
        int s = g_csrc[start + i];
        float2 v = reinterpret_cast<const float2*>(g_h2 + s * OUTF)[lane];
        acc.x += v.x;
        acc.y += v.y;
    }
    float dc = g_dinv[c];
    float2 self = reinterpret_cast<const float2*>(g_h2 + c * OUTF)[lane];
    float2 bb = reinterpret_cast<const float2*>(b2)[lane];
    float2 r;
    r.x = dc * (acc.x + self.x) + bb.x;
    r.y = dc * (acc.y + self.y) + bb.y;
    reinterpret_cast<float2*>(out + c * OUTF)[lane] = r;
}

extern "C" void kernel_launch(void* const* d_in, const int* in_sizes, int n_in,
                              void* d_out, int out_size) {
    const float* x   = (const float*)d_in[0];
    const int*   ei  = (const int*)d_in[1];   // int32 (JAX x64 disabled)
    const float* W1  = (const float*)d_in[2];
    const float* b1  = (const float*)d_in[3];
    const float* W2  = (const float*)d_in[4];
    const float* b2  = (const float*)d_in[5];
    float*       out = (float*)d_out;

    const int E = in_sizes[1] / 2;
    const int* row = ei;       // sources
    const int* col = ei + E;   // targets (aggregation index)

    const int T = 256;
    auto cdiv = [](long long a, long long b) { return (int)((a + b - 1) / b); };

    // CSR build + norms (parallel coalesced scan)
    k_zero<<<cdiv(NN, T), T>>>();
    k_hist<<<cdiv(E, T), T>>>(col, E);
    k_blocksum<<<NBLK, SCAN_B>>>();
    k_scanbsum<<<1, 128>>>();
    k_applyscan<<<NBLK, SCAN_B>>>();
    k_scatter<<<cdiv(E, T), T>>>(row, col, E);

    // layer 1 transform + fused agg/relu/transform2
    k_gemm1<<<cdiv(NN, 64), 128>>>(x, W1);
    k_agg1g2<<<cdiv((long long)NN * 32, T), T>>>(b1, W2);

    // layer 2 aggregation -> final output
    k_agg2<<<cdiv((long long)NN * 32, T), T>>>(out, b2);
}

// round 5
// speedup vs baseline: 2.3060x; 1.0733x over previous
#include <cuda_runtime.h>
#include <cstdint>

#define NN    100000
#define INC   128
#define HIDF  16
#define OUTF  64
#define EMAX  3200000
#define SCAN_B 1024
#define NBLK  ((NN + SCAN_B - 1) / SCAN_B)   // 98

// ---- Scratch (static device globals — no allocation allowed) ----
__device__ __align__(16) float g_dinv[NN];
__device__ __align__(16) float g_h1[NN * HIDF];   // ĥ1 = dinv * (x@W1)
__device__ __align__(16) float g_ha[NN * HIDF];   // â  = dinv * relu(out1)
__device__ int g_cnt[NN];
__device__ int g_rowstart[NN];
__device__ int g_cursor[NN];
__device__ int g_csrc[EMAX];
__device__ int g_bsum[NBLK];

// ---------------- zero counters ----------------
__global__ void k_zero() {
    int i = blockIdx.x * blockDim.x + threadIdx.x;
    if (i < NN) g_cnt[i] = 0;
}

// ---------------- histogram by target ----------------
__global__ void k_hist(const int* __restrict__ col, int E) {
    int i = blockIdx.x * blockDim.x + threadIdx.x;
    if (i < E) atomicAdd(&g_cnt[col[i]], 1);
}

// ---------------- scan stage 1: coalesced per-block sums ----------------
__global__ void k_blocksum() {
    __shared__ int wsum[32];
    int i = blockIdx.x * SCAN_B + threadIdx.x;
    int v = (i < NN) ? g_cnt[i] : 0;
    #pragma unroll
    for (int o = 16; o > 0; o >>= 1) v += __shfl_xor_sync(0xFFFFFFFFu, v, o);
    int warp = threadIdx.x >> 5, lane = threadIdx.x & 31;
    if (lane == 0) wsum[warp] = v;
    __syncthreads();
    if (warp == 0) {
        int s = (lane < SCAN_B / 32) ? wsum[lane] : 0;
        #pragma unroll
        for (int o = 16; o > 0; o >>= 1) s += __shfl_xor_sync(0xFFFFFFFFu, s, o);
        if (lane == 0) g_bsum[blockIdx.x] = s;
    }
}

// ---------------- scan stage 2: per-block scan (block offset computed redundantly) + dinv ----------------
__global__ void k_applyscan() {
    __shared__ int sb[128];
    __shared__ int wtot[33];
    int t = threadIdx.x;
    // redundant scan of the 98 block sums (inclusive)
    if (t < 128) sb[t] = (t < NBLK) ? g_bsum[t] : 0;
    __syncthreads();
    for (int off = 1; off < 128; off <<= 1) {
        int y = (t < 128 && t >= off) ? sb[t - off] : 0;
        __syncthreads();
        if (t < 128) sb[t] += y;
        __syncthreads();
    }
    int boff = (blockIdx.x == 0) ? 0 : sb[blockIdx.x - 1];

    int i = blockIdx.x * SCAN_B + t;
    int warp = t >> 5, lane = t & 31;
    int v = (i < NN) ? g_cnt[i] : 0;
    int x = v;
    #pragma unroll
    for (int o = 1; o < 32; o <<= 1) {
        int y = __shfl_up_sync(0xFFFFFFFFu, x, o);
        if (lane >= o) x += y;
    }
    if (lane == 31) wtot[warp] = x;
    __syncthreads();
    if (warp == 0) {
        int w = (lane < SCAN_B / 32) ? wtot[lane] : 0;
        int wx = w;
        #pragma unroll
        for (int o = 1; o < 32; o <<= 1) {
            int y = __shfl_up_sync(0xFFFFFFFFu, wx, o);
            if (lane >= o) wx += y;
        }
        wtot[lane + 1] = wx;
        if (lane == 0) wtot[0] = 0;
    }
    __syncthreads();
    if (i < NN) {
        int start = boff + wtot[warp] + (x - v);
        g_rowstart[i] = start;
        g_cursor[i]   = start;
        g_dinv[i]     = rsqrtf((float)(v + 1));
    }
}

// ---------------- scatter edges into CSR (sorted by target) ----------------
__global__ void k_scatter(const int* __restrict__ row, const int* __restrict__ col, int E) {
    int e = blockIdx.x * blockDim.x + threadIdx.x;
    if (e >= E) return;
    int c = col[e];
    int pos = atomicAdd(&g_cursor[c], 1);
    g_csrc[pos] = row[e];
}

// ---------------- GEMM1: ĥ1 = dinv * (x @ W1) (register-tiled 2n x 4h) ----------------
__global__ void k_gemm1(const float* __restrict__ x, const float* __restrict__ W1) {
    __shared__ float sX[64 * 129];
    __shared__ __align__(16) float sW[INC * HIDF];
    int tid = threadIdx.x;
    int nodeBase = blockIdx.x * 64;
    for (int i = tid; i < INC * HIDF; i += 128) sW[i] = W1[i];
    for (int i = tid; i < 64 * INC; i += 128) {
        int r = i >> 7, ck = i & 127;
        int node = nodeBase + r;
        sX[r * 129 + ck] = (node < NN) ? x[(size_t)node * INC + ck] : 0.0f;
    }
    __syncthreads();
    int npair = tid >> 2;
    int hq    = tid & 3;
    float4 acc0 = {0, 0, 0, 0}, acc1 = {0, 0, 0, 0};
    const float* xr0 = sX + (npair * 2) * 129;
    const float* xr1 = xr0 + 129;
    #pragma unroll 8
    for (int k = 0; k < INC; k++) {
        float  xa = xr0[k], xb = xr1[k];
        float4 w  = *reinterpret_cast<const float4*>(sW + k * HIDF + hq * 4);
        acc0.x += xa * w.x; acc0.y += xa * w.y; acc0.z += xa * w.z; acc0.w += xa * w.w;
        acc1.x += xb * w.x; acc1.y += xb * w.y; acc1.z += xb * w.z; acc1.w += xb * w.w;
    }
    int n0 = nodeBase + npair * 2;
    if (n0 < NN) {
        float d = g_dinv[n0];
        acc0.x *= d; acc0.y *= d; acc0.z *= d; acc0.w *= d;
        *reinterpret_cast<float4*>(g_h1 + n0 * HIDF + hq * 4) = acc0;
    }
    if (n0 + 1 < NN) {
        float d = g_dinv[n0 + 1];
        acc1.x *= d; acc1.y *= d; acc1.z *= d; acc1.w *= d;
        *reinterpret_cast<float4*>(g_h1 + (n0 + 1) * HIDF + hq * 4) = acc1;
    }
}

// ---------------- agg1 + ReLU + prescale: â = dinv * relu(dc*(Σ ĥ1 + ĥ1[c]) + b1) ----------------
__global__ void k_agg1(const float* __restrict__ b1) {
    int warpg = (blockIdx.x * blockDim.x + threadIdx.x) >> 5;
    int lane = threadIdx.x & 31;
    if (warpg >= NN) return;
    int c = warpg;
    int f = lane & 15, half = lane >> 4;
    int start = g_rowstart[c], deg = g_cnt[c];
    float acc = 0.0f;
    int i = half;
    for (; i + 6 < deg; i += 8) {      // 4 gathers per half in flight
        int s0 = g_csrc[start + i];
        int s1 = g_csrc[start + i + 2];
        int s2 = g_csrc[start + i + 4];
        int s3 = g_csrc[start + i + 6];
        acc += g_h1[s0 * HIDF + f] + g_h1[s1 * HIDF + f]
             + g_h1[s2 * HIDF + f] + g_h1[s3 * HIDF + f];
    }
    for (; i < deg; i += 2) {
        int s = g_csrc[start + i];
        acc += g_h1[s * HIDF + f];
    }
    acc += __shfl_xor_sync(0xFFFFFFFFu, acc, 16);
    if (half == 0) {
        float dc = g_dinv[c];
        float a = dc * (acc + g_h1[c * HIDF + f]) + b1[f];
        g_ha[c * HIDF + f] = dc * fmaxf(a, 0.0f);    // prescaled for layer-2 agg
    }
}

// ---------------- fused agg2 + GEMM2: out = (dc*(Σ â + â[c])) @ W2 + b2 ----------------
__global__ void k_agg2g2(float* __restrict__ out, const float* __restrict__ W2,
                         const float* __restrict__ b2) {
    __shared__ float sW[HIDF * OUTF];   // 4 KB
    int tid = threadIdx.x;
    for (int i = tid; i < HIDF * OUTF; i += blockDim.x) sW[i] = W2[i];
    __syncthreads();
    int warpg = (blockIdx.x * blockDim.x + tid) >> 5;
    int lane = tid & 31;
    if (warpg >= NN) return;
    int c = warpg;
    int f = lane & 15, half = lane >> 4;
    int start = g_rowstart[c], deg = g_cnt[c];
    float acc = 0.0f;
    int i = half;
    for (; i + 6 < deg; i += 8) {
        int s0 = g_csrc[start + i];
        int s1 = g_csrc[start + i + 2];
        int s2 = g_csrc[start + i + 4];
        int s3 = g_csrc[start + i + 6];
        acc += g_ha[s0 * HIDF + f] + g_ha[s1 * HIDF + f]
             + g_ha[s2 * HIDF + f] + g_ha[s3 * HIDF + f];
    }
    for (; i < deg; i += 2) {
        int s = g_csrc[start + i];
        acc += g_ha[s * HIDF + f];
    }
    acc += __shfl_xor_sync(0xFFFFFFFFu, acc, 16);   // all lanes hold sum for feature f
    float dc = g_dinv[c];
    float t = dc * (acc + g_ha[c * HIDF + f]);      // aggregated 16-vec (lanes 0..15 valid)
    // matvec: lane computes outputs 2*lane, 2*lane+1
    float2 o = {0.0f, 0.0f};
    #pragma unroll
    for (int k = 0; k < HIDF; k++) {
        float tk = __shfl_sync(0xFFFFFFFFu, t, k);
        float2 w = reinterpret_cast<const float2*>(sW + k * OUTF)[lane];
        o.x += tk * w.x;
        o.y += tk * w.y;
    }
    float2 bb = reinterpret_cast<const float2*>(b2)[lane];
    o.x += bb.x; o.y += bb.y;
    reinterpret_cast<float2*>(out + c * OUTF)[lane] = o;
}

extern "C" void kernel_launch(void* const* d_in, const int* in_sizes, int n_in,
                              void* d_out, int out_size) {
    const float* x   = (const float*)d_in[0];
    const int*   ei  = (const int*)d_in[1];   // int32 (JAX x64 disabled)
    const float* W1  = (const float*)d_in[2];
    const float* b1  = (const float*)d_in[3];
    const float* W2  = (const float*)d_in[4];
    const float* b2  = (const float*)d_in[5];
    float*       out = (float*)d_out;

    const int E = in_sizes[1] / 2;
    const int* row = ei;       // sources
    const int* col = ei + E;   // targets

    const int T = 256;
    auto cdiv = [](long long a, long long b) { return (int)((a + b - 1) / b); };

    // CSR build + norms
    k_zero<<<cdiv(NN, T), T>>>();
    k_hist<<<cdiv(E, T), T>>>(col, E);
    k_blocksum<<<NBLK, SCAN_B>>>();
    k_applyscan<<<NBLK, SCAN_B>>>();
    k_scatter<<<cdiv(E, T), T>>>(row, col, E);

    // layer 1
    k_gemm1<<<cdiv(NN, 64), 128>>>(x, W1);
    k_agg1<<<cdiv((long long)NN * 32, T), T>>>(b1);

    // layer 2 (aggregate 16-wide, then transform)
    k_agg2g2<<<cdiv((long long)NN * 32, T), T>>>(out, W2, b2);
}

// round 6
// speedup vs baseline: 2.4772x; 1.0743x over previous
#include <cuda_runtime.h>
#include <cstdint>

#define NN    100000
#define INC   128
#define HIDF  16
#define OUTF  64
#define EMAX  3200000
#define SCAN_B 1024
#define NBLK  ((NN + SCAN_B - 1) / SCAN_B)   // 98

// ---- Scratch (static device globals — no allocation allowed) ----
__device__ __align__(16) float g_dinv[NN];
__device__ __align__(16) float g_h1[NN * HIDF];   // ĥ1 = dinv * (x@W1)
__device__ __align__(16) float g_ha[NN * HIDF];   // â  = dinv * relu(out1)
__device__ int g_cnt[NN];
__device__ int g_rowstart[NN];
__device__ int g_cursor[NN];
__device__ int g_csrc[EMAX];
__device__ int g_bsum[NBLK];

// ---------------- zero counters ----------------
__global__ void k_zero() {
    int i = blockIdx.x * blockDim.x + threadIdx.x;
    if (i < NN) g_cnt[i] = 0;
}

// ---------------- histogram by target ----------------
__global__ void k_hist(const int* __restrict__ col, int E) {
    int i = blockIdx.x * blockDim.x + threadIdx.x;
    if (i < E) atomicAdd(&g_cnt[col[i]], 1);
}

// ---------------- scan stage 1: coalesced per-block sums ----------------
__global__ void k_blocksum() {
    __shared__ int wsum[32];
    int i = blockIdx.x * SCAN_B + threadIdx.x;
    int v = (i < NN) ? g_cnt[i] : 0;
    #pragma unroll
    for (int o = 16; o > 0; o >>= 1) v += __shfl_xor_sync(0xFFFFFFFFu, v, o);
    int warp = threadIdx.x >> 5, lane = threadIdx.x & 31;
    if (lane == 0) wsum[warp] = v;
    __syncthreads();
    if (warp == 0) {
        int s = (lane < SCAN_B / 32) ? wsum[lane] : 0;
        #pragma unroll
        for (int o = 16; o > 0; o >>= 1) s += __shfl_xor_sync(0xFFFFFFFFu, s, o);
        if (lane == 0) g_bsum[blockIdx.x] = s;
    }
}

// ---------------- scan stage 2: per-block scan (block offset redundant) + dinv ----------------
__global__ void k_applyscan() {
    __shared__ int sb[128];
    __shared__ int wtot[33];
    int t = threadIdx.x;
    if (t < 128) sb[t] = (t < NBLK) ? g_bsum[t] : 0;
    __syncthreads();
    for (int off = 1; off < 128; off <<= 1) {
        int y = (t < 128 && t >= off) ? sb[t - off] : 0;
        __syncthreads();
        if (t < 128) sb[t] += y;
        __syncthreads();
    }
    int boff = (blockIdx.x == 0) ? 0 : sb[blockIdx.x - 1];

    int i = blockIdx.x * SCAN_B + t;
    int warp = t >> 5, lane = t & 31;
    int v = (i < NN) ? g_cnt[i] : 0;
    int x = v;
    #pragma unroll
    for (int o = 1; o < 32; o <<= 1) {
        int y = __shfl_up_sync(0xFFFFFFFFu, x, o);
        if (lane >= o) x += y;
    }
    if (lane == 31) wtot[warp] = x;
    __syncthreads();
    if (warp == 0) {
        int w = (lane < SCAN_B / 32) ? wtot[lane] : 0;
        int wx = w;
        #pragma unroll
        for (int o = 1; o < 32; o <<= 1) {
            int y = __shfl_up_sync(0xFFFFFFFFu, wx, o);
            if (lane >= o) wx += y;
        }
        wtot[lane + 1] = wx;
        if (lane == 0) wtot[0] = 0;
    }
    __syncthreads();
    if (i < NN) {
        int start = boff + wtot[warp] + (x - v);
        g_rowstart[i] = start;
        g_cursor[i]   = start;
        g_dinv[i]     = rsqrtf((float)(v + 1));
    }
}

// ---------------- scatter edges into CSR (sorted by target) ----------------
__global__ void k_scatter(const int* __restrict__ row, const int* __restrict__ col, int E) {
    int e = blockIdx.x * blockDim.x + threadIdx.x;
    if (e >= E) return;
    int c = col[e];
    int pos = atomicAdd(&g_cursor[c], 1);
    g_csrc[pos] = row[e];
}

// ---------------- GEMM1: ĥ1 = dinv * (x @ W1) (register-tiled 2n x 4h) ----------------
__global__ void k_gemm1(const float* __restrict__ x, const float* __restrict__ W1) {
    __shared__ float sX[64 * 129];
    __shared__ __align__(16) float sW[INC * HIDF];
    int tid = threadIdx.x;
    int nodeBase = blockIdx.x * 64;
    for (int i = tid; i < INC * HIDF; i += 128) sW[i] = W1[i];
    for (int i = tid; i < 64 * INC; i += 128) {
        int r = i >> 7, ck = i & 127;
        int node = nodeBase + r;
        sX[r * 129 + ck] = (node < NN) ? x[(size_t)node * INC + ck] : 0.0f;
    }
    __syncthreads();
    int npair = tid >> 2;
    int hq    = tid & 3;
    float4 acc0 = {0, 0, 0, 0}, acc1 = {0, 0, 0, 0};
    const float* xr0 = sX + (npair * 2) * 129;
    const float* xr1 = xr0 + 129;
    #pragma unroll 8
    for (int k = 0; k < INC; k++) {
        float  xa = xr0[k], xb = xr1[k];
        float4 w  = *reinterpret_cast<const float4*>(sW + k * HIDF + hq * 4);
        acc0.x += xa * w.x; acc0.y += xa * w.y; acc0.z += xa * w.z; acc0.w += xa * w.w;
        acc1.x += xb * w.x; acc1.y += xb * w.y; acc1.z += xb * w.z; acc1.w += xb * w.w;
    }
    int n0 = nodeBase + npair * 2;
    if (n0 < NN) {
        float d = g_dinv[n0];
        acc0.x *= d; acc0.y *= d; acc0.z *= d; acc0.w *= d;
        *reinterpret_cast<float4*>(g_h1 + n0 * HIDF + hq * 4) = acc0;
    }
    if (n0 + 1 < NN) {
        float d = g_dinv[n0 + 1];
        acc1.x *= d; acc1.y *= d; acc1.z *= d; acc1.w *= d;
        *reinterpret_cast<float4*>(g_h1 + (n0 + 1) * HIDF + hq * 4) = acc1;
    }
}

// Reduce a float4 across the 8 edge-slots (lanes with same lane&3).
__device__ __forceinline__ float4 quad_reduce(float4 a) {
    #pragma unroll
    for (int m = 4; m <= 16; m <<= 1) {
        a.x += __shfl_xor_sync(0xFFFFFFFFu, a.x, m);
        a.y += __shfl_xor_sync(0xFFFFFFFFu, a.y, m);
        a.z += __shfl_xor_sync(0xFFFFFFFFu, a.z, m);
        a.w += __shfl_xor_sync(0xFFFFFFFFu, a.w, m);
    }
    return a;
}

// ---------------- agg1: warp/node, 4 lanes per edge, float4 gathers ----------------
// â = dinv * relu(dc*(Σ ĥ1 + ĥ1[c]) + b1)
__global__ void k_agg1(const float* __restrict__ b1) {
    int warpg = (blockIdx.x * blockDim.x + threadIdx.x) >> 5;
    int lane = threadIdx.x & 31;
    if (warpg >= NN) return;
    int c = warpg;
    int q = lane & 3;        // feature quad
    int es = lane >> 2;      // edge slot 0..7
    int start = g_rowstart[c], deg = g_cnt[c];
    float4 acc = {0, 0, 0, 0};
    int i = 0;
    for (; i + 16 <= deg; i += 16) {
        int sA = g_csrc[start + i + es];
        int sB = g_csrc[start + i + 8 + es];
        float4 vA = *reinterpret_cast<const float4*>(g_h1 + sA * HIDF + q * 4);
        float4 vB = *reinterpret_cast<const float4*>(g_h1 + sB * HIDF + q * 4);
        acc.x += vA.x + vB.x; acc.y += vA.y + vB.y;
        acc.z += vA.z + vB.z; acc.w += vA.w + vB.w;
    }
    for (; i < deg; i += 8) {
        int e = i + es;
        if (e < deg) {
            int s = g_csrc[start + e];
            float4 v = *reinterpret_cast<const float4*>(g_h1 + s * HIDF + q * 4);
            acc.x += v.x; acc.y += v.y; acc.z += v.z; acc.w += v.w;
        }
    }
    acc = quad_reduce(acc);
    float dc = g_dinv[c];
    float4 self = *reinterpret_cast<const float4*>(g_h1 + c * HIDF + q * 4);
    float4 bb = reinterpret_cast<const float4*>(b1)[q];
    float4 a;
    a.x = fmaxf(dc * (acc.x + self.x) + bb.x, 0.0f) * dc;
    a.y = fmaxf(dc * (acc.y + self.y) + bb.y, 0.0f) * dc;
    a.z = fmaxf(dc * (acc.z + self.z) + bb.z, 0.0f) * dc;
    a.w = fmaxf(dc * (acc.w + self.w) + bb.w, 0.0f) * dc;
    if (es == 0) *reinterpret_cast<float4*>(g_ha + c * HIDF + q * 4) = a;
}

// ---------------- fused agg2 + GEMM2: out = (dc*(Σ â + â[c])) @ W2 + b2 ----------------
__global__ void k_agg2g2(float* __restrict__ out, const float* __restrict__ W2,
                         const float* __restrict__ b2) {
    __shared__ float sW[HIDF * OUTF];   // 4 KB
    int tid = threadIdx.x;
    for (int i = tid; i < HIDF * OUTF; i += blockDim.x) sW[i] = W2[i];
    __syncthreads();
    int warpg = (blockIdx.x * blockDim.x + tid) >> 5;
    int lane = tid & 31;
    if (warpg >= NN) return;
    int c = warpg;
    int q = lane & 3;
    int es = lane >> 2;
    int start = g_rowstart[c], deg = g_cnt[c];
    float4 acc = {0, 0, 0, 0};
    int i = 0;
    for (; i + 16 <= deg; i += 16) {
        int sA = g_csrc[start + i + es];
        int sB = g_csrc[start + i + 8 + es];
        float4 vA = *reinterpret_cast<const float4*>(g_ha + sA * HIDF + q * 4);
        float4 vB = *reinterpret_cast<const float4*>(g_ha + sB * HIDF + q * 4);
        acc.x += vA.x + vB.x; acc.y += vA.y + vB.y;
        acc.z += vA.z + vB.z; acc.w += vA.w + vB.w;
    }
    for (; i < deg; i += 8) {
        int e = i + es;
        if (e < deg) {
            int s = g_csrc[start + e];
            float4 v = *reinterpret_cast<const float4*>(g_ha + s * HIDF + q * 4);
            acc.x += v.x; acc.y += v.y; acc.z += v.z; acc.w += v.w;
        }
    }
    acc = quad_reduce(acc);
    float dc = g_dinv[c];
    float4 self = *reinterpret_cast<const float4*>(g_ha + c * HIDF + q * 4);
    float4 t;
    t.x = dc * (acc.x + self.x);
    t.y = dc * (acc.y + self.y);
    t.z = dc * (acc.z + self.z);
    t.w = dc * (acc.w + self.w);
    // matvec: feature k lives in component (k&3) of lane (k>>2) (replicated across es)
    float2 o = {0.0f, 0.0f};
    #pragma unroll
    for (int k = 0; k < HIDF; k++) {
        float comp = ((k & 3) == 0) ? t.x : ((k & 3) == 1) ? t.y : ((k & 3) == 2) ? t.z : t.w;
        float tk = __shfl_sync(0xFFFFFFFFu, comp, k >> 2);
        float2 w = reinterpret_cast<const float2*>(sW + k * OUTF)[lane];
        o.x += tk * w.x;
        o.y += tk * w.y;
    }
    float2 bb = reinterpret_cast<const float2*>(b2)[lane];
    o.x += bb.x; o.y += bb.y;
    reinterpret_cast<float2*>(out + c * OUTF)[lane] = o;
}

extern "C" void kernel_launch(void* const* d_in, const int* in_sizes, int n_in,
                              void* d_out, int out_size) {
    const float* x   = (const float*)d_in[0];
    const int*   ei  = (const int*)d_in[1];   // int32 (JAX x64 disabled)
    const float* W1  = (const float*)d_in[2];
    const float* b1  = (const float*)d_in[3];
    const float* W2  = (const float*)d_in[4];
    const float* b2  = (const float*)d_in[5];
    float*       out = (float*)d_out;

    const int E = in_sizes[1] / 2;
    const int* row = ei;
    const int* col = ei + E;

    const int T = 256;
    auto cdiv = [](long long a, long long b) { return (int)((a + b - 1) / b); };

    k_zero<<<cdiv(NN, T), T>>>();
    k_hist<<<cdiv(E, T), T>>>(col, E);
    k_blocksum<<<NBLK, SCAN_B>>>();
    k_applyscan<<<NBLK, SCAN_B>>>();
    k_scatter<<<cdiv(E, T), T>>>(row, col, E);

    k_gemm1<<<cdiv(NN, 64), 128>>>(x, W1);
    k_agg1<<<cdiv((long long)NN * 32, T), T>>>(b1);
    k_agg2g2<<<cdiv((long long)NN * 32, T), T>>>(out, W2, b2);
}

// round 7
// speedup vs baseline: 2.6209x; 1.0580x over previous
#include <cuda_runtime.h>
#include <cstdint>

#define NN    100000
#define INC   128
#define HIDF  16
#define OUTF  64
#define EMAX  3200000
#define SCAN_B 1024
#define NBLK  ((NN + SCAN_B - 1) / SCAN_B)   // 98

// ---- Scratch (static device globals — zero-initialized at load) ----
__device__ __align__(16) float g_dinv[NN];
__device__ __align__(16) float g_h1[NN * HIDF];   // ĥ1 = dinv * (x@W1)
__device__ __align__(16) float g_ha[NN * HIDF];   // â  = dinv * relu(out1)
__device__ int g_cnt[NN];          // transient per-call histogram (self-cleaning)
__device__ int g_rowstart[NN];
__device__ int g_cursor[NN];       // after scatter: row END
__device__ int g_csrc[EMAX];
__device__ int g_bsum[NBLK];

// ---------------- histogram by target (g_cnt is zero on entry every call) ----------------
__global__ void k_hist(const int* __restrict__ col, int E) {
    int i = blockIdx.x * blockDim.x + threadIdx.x;
    if (i < E) atomicAdd(&g_cnt[col[i]], 1);
}

// ---------------- scan stage 1: coalesced per-block sums ----------------
__global__ void k_blocksum() {
    __shared__ int wsum[32];
    int i = blockIdx.x * SCAN_B + threadIdx.x;
    int v = (i < NN) ? g_cnt[i] : 0;
    #pragma unroll
    for (int o = 16; o > 0; o >>= 1) v += __shfl_xor_sync(0xFFFFFFFFu, v, o);
    int warp = threadIdx.x >> 5, lane = threadIdx.x & 31;
    if (lane == 0) wsum[warp] = v;
    __syncthreads();
    if (warp == 0) {
        int s = (lane < SCAN_B / 32) ? wsum[lane] : 0;
        #pragma unroll
        for (int o = 16; o > 0; o >>= 1) s += __shfl_xor_sync(0xFFFFFFFFu, s, o);
        if (lane == 0) g_bsum[blockIdx.x] = s;
    }
}

// ---------------- scan stage 2: per-block scan + dinv + self-clean g_cnt ----------------
__global__ void k_applyscan() {
    __shared__ int sb[128];
    __shared__ int wtot[33];
    int t = threadIdx.x;
    if (t < 128) sb[t] = (t < NBLK) ? g_bsum[t] : 0;
    __syncthreads();
    for (int off = 1; off < 128; off <<= 1) {
        int y = (t < 128 && t >= off) ? sb[t - off] : 0;
        __syncthreads();
        if (t < 128) sb[t] += y;
        __syncthreads();
    }
    int boff = (blockIdx.x == 0) ? 0 : sb[blockIdx.x - 1];

    int i = blockIdx.x * SCAN_B + t;
    int warp = t >> 5, lane = t & 31;
    int v = (i < NN) ? g_cnt[i] : 0;
    int x = v;
    #pragma unroll
    for (int o = 1; o < 32; o <<= 1) {
        int y = __shfl_up_sync(0xFFFFFFFFu, x, o);
        if (lane >= o) x += y;
    }
    if (lane == 31) wtot[warp] = x;
    __syncthreads();
    if (warp == 0) {
        int w = (lane < SCAN_B / 32) ? wtot[lane] : 0;
        int wx = w;
        #pragma unroll
        for (int o = 1; o < 32; o <<= 1) {
            int y = __shfl_up_sync(0xFFFFFFFFu, wx, o);
            if (lane >= o) wx += y;
        }
        wtot[lane + 1] = wx;
        if (lane == 0) wtot[0] = 0;
    }
    __syncthreads();
    if (i < NN) {
        int start = boff + wtot[warp] + (x - v);
        g_rowstart[i] = start;
        g_cursor[i]   = start;
        g_dinv[i]     = rsqrtf((float)(v + 1));
        g_cnt[i]      = 0;     // self-clean for next call (zero-init covers first call)
    }
}

// ---------------- GEMM1: ĥ1 = dinv * (x @ W1), thread = 4 nodes x 4 features ----------------
// 128 threads/block, 128 nodes/block. sX stride 129 (4*129 % 32 = 4 -> conflict-free).
__global__ void k_gemm1(const float* __restrict__ x, const float* __restrict__ W1) {
    __shared__ float sX[128 * 129];                 // ~66 KB
    __shared__ __align__(16) float sW[INC * HIDF];  // 8 KB
    int tid = threadIdx.x;
    int nodeBase = blockIdx.x * 128;
    for (int i = tid; i < INC * HIDF; i += 128) sW[i] = W1[i];
    // stage 128 rows: LDG.128 + 4x STS.32
    for (int i = tid; i < 128 * 32; i += 128) {
        int r = i >> 5, kq = i & 31;
        int node = nodeBase + r;
        float4 v = {0, 0, 0, 0};
        if (node < NN) v = *reinterpret_cast<const float4*>(x + (size_t)node * INC + kq * 4);
        float* d = sX + r * 129 + kq * 4;
        d[0] = v.x; d[1] = v.y; d[2] = v.z; d[3] = v.w;
    }
    __syncthreads();
    int nq = tid >> 2;          // node quad 0..31 -> nodes 4*nq..4*nq+3
    int hq = tid & 3;           // feature quad
    float4 a0 = {0,0,0,0}, a1 = {0,0,0,0}, a2 = {0,0,0,0}, a3 = {0,0,0,0};
    const float* x0 = sX + (nq * 4 + 0) * 129;
    const float* x1 = x0 + 129;
    const float* x2 = x1 + 129;
    const float* x3 = x2 + 129;
    #pragma unroll 4
    for (int k = 0; k < INC; k++) {
        float4 w = *reinterpret_cast<const float4*>(sW + k * HIDF + hq * 4);
        float v0 = x0[k], v1 = x1[k], v2 = x2[k], v3 = x3[k];
        a0.x += v0 * w.x; a0.y += v0 * w.y; a0.z += v0 * w.z; a0.w += v0 * w.w;
        a1.x += v1 * w.x; a1.y += v1 * w.y; a1.z += v1 * w.z; a1.w += v1 * w.w;
        a2.x += v2 * w.x; a2.y += v2 * w.y; a2.z += v2 * w.z; a2.w += v2 * w.w;
        a3.x += v3 * w.x; a3.y += v3 * w.y; a3.z += v3 * w.z; a3.w += v3 * w.w;
    }
    int n0 = nodeBase + nq * 4;
    float4 accs[4] = {a0, a1, a2, a3};
    #pragma unroll
    for (int j = 0; j < 4; j++) {
        int n = n0 + j;
        if (n < NN) {
            float d = g_dinv[n];
            float4 a = accs[j];
            a.x *= d; a.y *= d; a.z *= d; a.w *= d;
            *reinterpret_cast<float4*>(g_h1 + n * HIDF + hq * 4) = a;
        }
    }
}

// ---------------- scatter edges into CSR (cursor ends at row end) ----------------
__global__ void k_scatter(const int* __restrict__ row, const int* __restrict__ col, int E) {
    int e = blockIdx.x * blockDim.x + threadIdx.x;
    if (e >= E) return;
    int c = col[e];
    int pos = atomicAdd(&g_cursor[c], 1);
    g_csrc[pos] = row[e];
}

// Reduce a float4 across the 8 edge-slots (lanes with same lane&3).
__device__ __forceinline__ float4 quad_reduce(float4 a) {
    #pragma unroll
    for (int m = 4; m <= 16; m <<= 1) {
        a.x += __shfl_xor_sync(0xFFFFFFFFu, a.x, m);
        a.y += __shfl_xor_sync(0xFFFFFFFFu, a.y, m);
        a.z += __shfl_xor_sync(0xFFFFFFFFu, a.z, m);
        a.w += __shfl_xor_sync(0xFFFFFFFFu, a.w, m);
    }
    return a;
}

// ---------------- agg1: warp/node, 4 lanes per edge, float4 gathers ----------------
__global__ void k_agg1(const float* __restrict__ b1) {
    int warpg = (blockIdx.x * blockDim.x + threadIdx.x) >> 5;
    int lane = threadIdx.x & 31;
    if (warpg >= NN) return;
    int c = warpg;
    int q = lane & 3;
    int es = lane >> 2;
    int start = g_rowstart[c];
    int end   = g_cursor[c];       // row end after scatter
    float4 acc = {0, 0, 0, 0};
    int i = start;
    for (; i + 16 <= end; i += 16) {
        int sA = g_csrc[i + es];
        int sB = g_csrc[i + 8 + es];
        float4 vA = *reinterpret_cast<const float4*>(g_h1 + sA * HIDF + q * 4);
        float4 vB = *reinterpret_cast<const float4*>(g_h1 + sB * HIDF + q * 4);
        acc.x += vA.x + vB.x; acc.y += vA.y + vB.y;
        acc.z += vA.z + vB.z; acc.w += vA.w + vB.w;
    }
    for (; i + 8 <= end; i += 8) {
        int s = g_csrc[i + es];
        float4 v = *reinterpret_cast<const float4*>(g_h1 + s * HIDF + q * 4);
        acc.x += v.x; acc.y += v.y; acc.z += v.z; acc.w += v.w;
    }
    if (i + es < end) {
        int s = g_csrc[i + es];
        float4 v = *reinterpret_cast<const float4*>(g_h1 + s * HIDF + q * 4);
        acc.x += v.x; acc.y += v.y; acc.z += v.z; acc.w += v.w;
    }
    acc = quad_reduce(acc);
    float dc = g_dinv[c];
    float4 self = *reinterpret_cast<const float4*>(g_h1 + c * HIDF + q * 4);
    float4 bb = reinterpret_cast<const float4*>(b1)[q];
    float4 a;
    a.x = fmaxf(dc * (acc.x + self.x) + bb.x, 0.0f) * dc;
    a.y = fmaxf(dc * (acc.y + self.y) + bb.y, 0.0f) * dc;
    a.z = fmaxf(dc * (acc.z + self.z) + bb.z, 0.0f) * dc;
    a.w = fmaxf(dc * (acc.w + self.w) + bb.w, 0.0f) * dc;
    if (es == 0) *reinterpret_cast<float4*>(g_ha + c * HIDF + q * 4) = a;
}

// ---------------- fused agg2 + GEMM2: out = (dc*(Σ â + â[c])) @ W2 + b2 ----------------
__global__ void k_agg2g2(float* __restrict__ out, const float* __restrict__ W2,
                         const float* __restrict__ b2) {
    __shared__ float sW[HIDF * OUTF];
    int tid = threadIdx.x;
    for (int i = tid; i < HIDF * OUTF; i += blockDim.x) sW[i] = W2[i];
    __syncthreads();
    int warpg = (blockIdx.x * blockDim.x + tid) >> 5;
    int lane = tid & 31;
    if (warpg >= NN) return;
    int c = warpg;
    int q = lane & 3;
    int es = lane >> 2;
    int start = g_rowstart[c];
    int end   = g_cursor[c];
    float4 acc = {0, 0, 0, 0};
    int i = start;
    for (; i + 16 <= end; i += 16) {
        int sA = g_csrc[i + es];
        int sB = g_csrc[i + 8 + es];
        float4 vA = *reinterpret_cast<const float4*>(g_ha + sA * HIDF + q * 4);
        float4 vB = *reinterpret_cast<const float4*>(g_ha + sB * HIDF + q * 4);
        acc.x += vA.x + vB.x; acc.y += vA.y + vB.y;
        acc.z += vA.z + vB.z; acc.w += vA.w + vB.w;
    }
    for (; i + 8 <= end; i += 8) {
        int s = g_csrc[i + es];
        float4 v = *reinterpret_cast<const float4*>(g_ha + s * HIDF + q * 4);
        acc.x += v.x; acc.y += v.y; acc.z += v.z; acc.w += v.w;
    }
    if (i + es < end) {
        int s = g_csrc[i + es];
        float4 v = *reinterpret_cast<const float4*>(g_ha + s * HIDF + q * 4);
        acc.x += v.x; acc.y += v.y; acc.z += v.z; acc.w += v.w;
    }
    acc = quad_reduce(acc);
    float dc = g_dinv[c];
    float4 self = *reinterpret_cast<const float4*>(g_ha + c * HIDF + q * 4);
    float4 t;
    t.x = dc * (acc.x + self.x);
    t.y = dc * (acc.y + self.y);
    t.z = dc * (acc.z + self.z);
    t.w = dc * (acc.w + self.w);
    float2 o = {0.0f, 0.0f};
    #pragma unroll
    for (int k = 0; k < HIDF; k++) {
        float comp = ((k & 3) == 0) ? t.x : ((k & 3) == 1) ? t.y : ((k & 3) == 2) ? t.z : t.w;
        float tk = __shfl_sync(0xFFFFFFFFu, comp, k >> 2);
        float2 w = reinterpret_cast<const float2*>(sW + k * OUTF)[lane];
        o.x += tk * w.x;
        o.y += tk * w.y;
    }
    float2 bb = reinterpret_cast<const float2*>(b2)[lane];
    o.x += bb.x; o.y += bb.y;
    reinterpret_cast<float2*>(out + c * OUTF)[lane] = o;
}

extern "C" void kernel_launch(void* const* d_in, const int* in_sizes, int n_in,
                              void* d_out, int out_size) {
    const float* x   = (const float*)d_in[0];
    const int*   ei  = (const int*)d_in[1];   // int32 (JAX x64 disabled)
    const float* W1  = (const float*)d_in[2];
    const float* b1  = (const float*)d_in[3];
    const float* W2  = (const float*)d_in[4];
    const float* b2  = (const float*)d_in[5];
    float*       out = (float*)d_out;

    const int E = in_sizes[1] / 2;
    const int* row = ei;
    const int* col = ei + E;

    const int T = 256;
    auto cdiv = [](long long a, long long b) { return (int)((a + b - 1) / b); };

    // launch index:            0        1          2            3 (profiled)
    k_hist<<<cdiv(E, T), T>>>(col, E);
    k_blocksum<<<NBLK, SCAN_B>>>();
    k_applyscan<<<NBLK, SCAN_B>>>();
    k_gemm1<<<cdiv(NN, 128), 128>>>(x, W1);
    // 4..6
    k_scatter<<<cdiv(E, T), T>>>(row, col, E);
    k_agg1<<<cdiv((long long)NN * 32, T), T>>>(b1);
    k_agg2g2<<<cdiv((long long)NN * 32, T), T>>>(out, W2, b2);
}